// round 7
// baseline (speedup 1.0000x reference)
#include <cuda_runtime.h>

#define BATCH    32768
#define SEQ      200
#define NTHREADS 128
#define NBLOCKS  (BATCH / NTHREADS)

// ---------------- scratch (static __device__, no allocation) ----------------
__device__ float4 g_Hh4[SEQ * BATCH];     // layer-1 h of H RNN, [t][b] = {h0,h1,h2,h3}
__device__ float4 g_Lh4[SEQ * BATCH];     // layer-1 h of L RNN
__device__ float  g_F[256 * BATCH];       // tanh features [Hf(128);Lf(128)] x [b]
__device__ float  g_dot[2 * BATCH];       // x·u partial dots (H part, L part)
__device__ float  g_u[400];               // Wp^T @ W3[40:80]
__device__ float  g_c0[1];                // b3 + bp·W3[40:80]
__device__ float  g_Wt[16 * 800 * 16];    // feat weights [(r*8+jc)][k][j16]

// ---------------- f32x2 packed helpers (Blackwell) ----------------
typedef unsigned long long ull;
__device__ __forceinline__ ull pk(float a, float b) {
    ull r; asm("mov.b64 %0, {%1,%2};" : "=l"(r) : "f"(a), "f"(b)); return r;
}
__device__ __forceinline__ float2 upk(ull v) {
    float2 f; asm("mov.b64 {%0,%1}, %2;" : "=f"(f.x), "=f"(f.y) : "l"(v)); return f;
}
__device__ __forceinline__ ull fma2(ull a, ull b, ull c) {
    ull d; asm("fma.rn.f32x2 %0, %1, %2, %3;" : "=l"(d) : "l"(a), "l"(b), "l"(c));
    return d;
}

// ---------------- activations ----------------
__device__ __forceinline__ float tanha(float x) {       // HW tanh, LSTM-only
    float y; asm("tanh.approx.f32 %0, %1;" : "=f"(y) : "f"(x)); return y;
}
__device__ __forceinline__ float siga(float x) {
    return fmaf(tanha(0.5f * x), 0.5f, 0.5f);
}
__device__ __forceinline__ float sigf(float x) {        // accurate, head
    return __fdividef(1.0f, 1.0f + __expf(-x));
}
__device__ __forceinline__ float tanhfast(float x) {
    return 1.0f - __fdividef(2.0f, __expf(2.0f * x) + 1.0f);
}

// ================= prep A: fold 'other' path into a 400-vector =================
__global__ void prep_u_kernel(const float* __restrict__ Wp, const float* __restrict__ bp,
                              const float* __restrict__ W3, const float* __restrict__ b3)
{
    int k = blockIdx.x * blockDim.x + threadIdx.x;
    if (k < 400) {
        float s = 0.0f;
#pragma unroll
        for (int j = 0; j < 40; j++) s = fmaf(W3[40 + j], Wp[j * 400 + k], s);
        g_u[k] = s;
    }
    if (k == 400) {
        float s = b3[0];
#pragma unroll
        for (int j = 0; j < 40; j++) s = fmaf(W3[40 + j], bp[j], s);
        g_c0[0] = s;
    }
}

// ================= prep B: coalesced transpose of feat weights =================
// g_Wt[blk][k][j] = W_r[(jc*16+j)*800 + k],  blk = r*8+jc,  k in 0..799, j in 0..15
__global__ void prep_w_kernel(const float* __restrict__ WH, const float* __restrict__ WL)
{
    __shared__ float sT[16][401];
    const int blk = blockIdx.x;            // 0..15
    const int r = blk >> 3, jc = blk & 7;
    const float* __restrict__ W = r ? WL : WH;
    const int tid = threadIdx.x;           // 256 threads
    float* __restrict__ dst = g_Wt + (size_t)blk * 800 * 16;

    for (int half = 0; half < 2; half++) {
        __syncthreads();
        for (int idx = tid; idx < 16 * 400; idx += 256) {
            int j = idx / 400, k = idx % 400;
            sT[j][k] = W[(size_t)(jc * 16 + j) * 800 + half * 400 + k];
        }
        __syncthreads();
        for (int idx = tid; idx < 400 * 16; idx += 256) {
            int k = idx >> 4, j = idx & 15;
            dst[(half * 400 + k) * 16 + j] = sT[j][k];
        }
    }
}

// ================= LSTM cell (H=4, gate order i,f,g,o) =================
__device__ __forceinline__ void cell_update(const float* g, float* h, float* c) {
#pragma unroll
    for (int k = 0; k < 4; k++) {
        float cn = siga(g[4 + k]) * c[k] + siga(g[k]) * tanha(g[8 + k]);
        c[k] = cn;
        h[k] = siga(g[12 + k]) * tanha(cn);
    }
}

// ================= Kernel 1: 2-layer LSTM, one channel per block =================
__global__ __launch_bounds__(NTHREADS) void lstm_kernel(
    const float* __restrict__ x,
    const float* __restrict__ w0ih0, const float* __restrict__ w0hh0,
    const float* __restrict__ b0ih0, const float* __restrict__ b0hh0,
    const float* __restrict__ w0ih1, const float* __restrict__ w0hh1,
    const float* __restrict__ b0ih1, const float* __restrict__ b0hh1,
    const float* __restrict__ w1ih0, const float* __restrict__ w1hh0,
    const float* __restrict__ b1ih0, const float* __restrict__ b1hh0,
    const float* __restrict__ w1ih1, const float* __restrict__ w1hh1,
    const float* __restrict__ b1ih1, const float* __restrict__ b1hh1)
{
    __shared__ ull sWih0[8], sB0[8], sB1[8];
    __shared__ ull sWhh0[32], sWih1[32], sWhh1[32];   // [k][pair] = k*8+p
    __shared__ float sX[NTHREADS][25];

    const int tid = threadIdx.x;
    const int ch  = blockIdx.y;
    const int b0  = blockIdx.x * NTHREADS;
    const int b   = b0 + tid;

    const float* wih0 = ch ? w1ih0 : w0ih0;
    const float* whh0 = ch ? w1hh0 : w0hh0;
    const float* bi0  = ch ? b1ih0 : b0ih0;
    const float* bh0  = ch ? b1hh0 : b0hh0;
    const float* wih1 = ch ? w1ih1 : w0ih1;
    const float* whh1 = ch ? w1hh1 : w0hh1;
    const float* bi1  = ch ? b1ih1 : b0ih1;
    const float* bh1  = ch ? b1hh1 : b0hh1;
    float4* __restrict__ hout4 = ch ? g_Lh4 : g_Hh4;

    if (tid < 8) {
        int p = tid;
        sWih0[p] = pk(wih0[2 * p], wih0[2 * p + 1]);
        sB0[p]   = pk(bi0[2 * p] + bh0[2 * p], bi0[2 * p + 1] + bh0[2 * p + 1]);
        sB1[p]   = pk(bi1[2 * p] + bh1[2 * p], bi1[2 * p + 1] + bh1[2 * p + 1]);
    }
    if (tid < 32) {
        int k = tid >> 3, p = tid & 7;
        sWhh0[tid] = pk(whh0[(2 * p) * 4 + k], whh0[(2 * p + 1) * 4 + k]);
        sWih1[tid] = pk(wih1[(2 * p) * 4 + k], wih1[(2 * p + 1) * 4 + k]);
        sWhh1[tid] = pk(whh1[(2 * p) * 4 + k], whh1[(2 * p + 1) * 4 + k]);
    }

    float h0[4], c0a[4], h1[4], c1[4];
#pragma unroll
    for (int k = 0; k < 4; k++) { h0[k] = c0a[k] = h1[k] = c1[k] = 0.0f; }
    float dacc = 0.0f;
    const float* uvec = g_u + ch * SEQ;

    for (int tile = 0; tile < 8; ++tile) {
        __syncthreads();
#pragma unroll
        for (int i = tid; i < NTHREADS * 25; i += NTHREADS) {
            int s = i / 25, tt = i % 25;
            sX[s][tt] = x[(size_t)(b0 + s) * (2 * SEQ) + ch * SEQ + tile * 25 + tt];
        }
        __syncthreads();

        for (int tt = 0; tt < 25; ++tt) {
            const int t = tile * 25 + tt;
            const float xh = sX[tid][tt];
            dacc = fmaf(xh, __ldg(&uvec[t]), dacc);

            ull v[8];
            {
                ull x2 = pk(xh, xh);
#pragma unroll
                for (int p = 0; p < 8; p++) v[p] = fma2(x2, sWih0[p], sB0[p]);
#pragma unroll
                for (int k = 0; k < 4; k++) {
                    ull h2 = pk(h0[k], h0[k]);
#pragma unroll
                    for (int p = 0; p < 8; p++) v[p] = fma2(h2, sWhh0[k * 8 + p], v[p]);
                }
            }
            float g[16];
#pragma unroll
            for (int p = 0; p < 8; p++) { float2 f = upk(v[p]); g[2 * p] = f.x; g[2 * p + 1] = f.y; }
            cell_update(g, h0, c0a);

#pragma unroll
            for (int p = 0; p < 8; p++) v[p] = sB1[p];
#pragma unroll
            for (int k = 0; k < 4; k++) {
                ull h2 = pk(h0[k], h0[k]);
#pragma unroll
                for (int p = 0; p < 8; p++) v[p] = fma2(h2, sWih1[k * 8 + p], v[p]);
            }
#pragma unroll
            for (int k = 0; k < 4; k++) {
                ull h2 = pk(h1[k], h1[k]);
#pragma unroll
                for (int p = 0; p < 8; p++) v[p] = fma2(h2, sWhh1[k * 8 + p], v[p]);
            }
#pragma unroll
            for (int p = 0; p < 8; p++) { float2 f = upk(v[p]); g[2 * p] = f.x; g[2 * p + 1] = f.y; }
            cell_update(g, h1, c1);

            hout4[(size_t)t * BATCH + b] = make_float4(h1[0], h1[1], h1[2], h1[3]);
        }
    }
    g_dot[ch * BATCH + b] = dacc;
}

// ================= Kernel 2: feature GEMM, 4 samples x 16 features / thread ======
// grid (BATCH/512, 16): y = r*8+jc
__global__ __launch_bounds__(NTHREADS) void feat_kernel(
    const float* __restrict__ bHv, const float* __restrict__ bLv)
{
    __shared__ __align__(16) float sW[400 * 16];     // 25.6 KB, [k-local][j]

    const int tid = threadIdx.x;
    const int bb0 = blockIdx.x * (NTHREADS * 4);
    const int y   = blockIdx.y;
    const int r   = y >> 3, jc = y & 7;
    const float*  __restrict__ bias = r ? bLv : bHv;
    const float4* __restrict__ hh4  = r ? g_Lh4 : g_Hh4;
    const int f0 = jc * 16;

    ull acc[4][8];
#pragma unroll
    for (int p = 0; p < 8; p++) {
        ull bv = pk(__ldg(&bias[f0 + 2 * p]), __ldg(&bias[f0 + 2 * p + 1]));
#pragma unroll
        for (int s = 0; s < 4; s++) acc[s][p] = bv;
    }

    const float* wt_base = g_Wt + (size_t)y * 800 * 16;

    for (int half = 0; half < 2; half++) {
        __syncthreads();
        const float4* src = reinterpret_cast<const float4*>(wt_base + half * 400 * 16);
#pragma unroll
        for (int i4 = tid; i4 < 1600; i4 += NTHREADS)
            reinterpret_cast<float4*>(sW)[i4] = __ldg(&src[i4]);
        __syncthreads();

#pragma unroll 1
        for (int tt = 0; tt < 100; ++tt) {
            const int t = half * 100 + tt;
            float ha[4][4];
#pragma unroll
            for (int s = 0; s < 4; s++) {
                float4 hv = __ldg(&hh4[(size_t)t * BATCH + bb0 + s * NTHREADS + tid]);
                ha[s][0] = hv.x; ha[s][1] = hv.y; ha[s][2] = hv.z; ha[s][3] = hv.w;
            }
#pragma unroll
            for (int kk = 0; kk < 4; kk++) {
                const ulonglong2* wp =
                    reinterpret_cast<const ulonglong2*>(sW + (tt * 4 + kk) * 16);
                ulonglong2 w0 = wp[0], w1 = wp[1], w2 = wp[2], w3 = wp[3];
#pragma unroll
                for (int s = 0; s < 4; s++) {
                    ull hd = pk(ha[s][kk], ha[s][kk]);
                    acc[s][0] = fma2(hd, w0.x, acc[s][0]);
                    acc[s][1] = fma2(hd, w0.y, acc[s][1]);
                    acc[s][2] = fma2(hd, w1.x, acc[s][2]);
                    acc[s][3] = fma2(hd, w1.y, acc[s][3]);
                    acc[s][4] = fma2(hd, w2.x, acc[s][4]);
                    acc[s][5] = fma2(hd, w2.y, acc[s][5]);
                    acc[s][6] = fma2(hd, w3.x, acc[s][6]);
                    acc[s][7] = fma2(hd, w3.y, acc[s][7]);
                }
            }
        }
    }

#pragma unroll
    for (int s = 0; s < 4; s++) {
        const int b = bb0 + s * NTHREADS + tid;
#pragma unroll
        for (int p = 0; p < 8; p++) {
            float2 f = upk(acc[s][p]);
            g_F[(size_t)(r * 128 + f0 + 2 * p) * BATCH + b]     = tanhfast(f.x);
            g_F[(size_t)(r * 128 + f0 + 2 * p + 1) * BATCH + b] = tanhfast(f.y);
        }
    }
}

// ================= Kernel 3: combine  256 -> 80 -> 40 -> 1  (8 threads/sample) ====
__global__ __launch_bounds__(NTHREADS) void combine_kernel(
    const float* __restrict__ W1, const float* __restrict__ b1,
    const float* __restrict__ W2, const float* __restrict__ b2,
    const float* __restrict__ W3,
    float* __restrict__ out)
{
    const int tid  = threadIdx.x;
    const int part = tid & 7;                       // eighth of the features
    const int b    = blockIdx.x * 16 + (tid >> 3);  // sample

    float acc1[80];
#pragma unroll
    for (int i = 0; i < 80; i++) acc1[i] = 0.0f;

#pragma unroll 1
    for (int q = 0; q < 8; ++q) {                   // 8 quads = 32 features per lane
        const int f0 = part * 32 + 4 * q;
        const float* fp = g_F + (size_t)f0 * BATCH + b;
        float v0 = __ldg(fp);
        float v1 = __ldg(fp + BATCH);
        float v2 = __ldg(fp + 2 * BATCH);
        float v3 = __ldg(fp + 3 * BATCH);
#pragma unroll
        for (int i = 0; i < 80; i++) {
            float4 w = __ldg(reinterpret_cast<const float4*>(W1 + (size_t)i * 256 + f0));
            float s = acc1[i];
            s = fmaf(v0, w.x, s);
            s = fmaf(v1, w.y, s);
            s = fmaf(v2, w.z, s);
            acc1[i] = fmaf(v3, w.w, s);
        }
    }
#pragma unroll
    for (int i = 0; i < 80; i++) {
        float s = acc1[i];
        s += __shfl_xor_sync(0xffffffffu, s, 1);
        s += __shfl_xor_sync(0xffffffffu, s, 2);
        s += __shfl_xor_sync(0xffffffffu, s, 4);
        acc1[i] = tanhfast(s + __ldg(&b1[i]));
    }

    float s3p = 0.0f;
#pragma unroll 1
    for (int r5 = 0; r5 < 5; ++r5) {                // 5 of the 40 W2 rows per lane
        const int i2 = part * 5 + r5;
        float s = __ldg(&b2[i2]);
        const float4* w4 = reinterpret_cast<const float4*>(W2 + (size_t)i2 * 80);
#pragma unroll
        for (int j4 = 0; j4 < 20; j4++) {
            float4 w = __ldg(&w4[j4]);
            s = fmaf(acc1[4 * j4 + 0], w.x, s);
            s = fmaf(acc1[4 * j4 + 1], w.y, s);
            s = fmaf(acc1[4 * j4 + 2], w.z, s);
            s = fmaf(acc1[4 * j4 + 3], w.w, s);
        }
        s3p = fmaf(tanhfast(s), __ldg(&W3[i2]), s3p);
    }
    s3p += __shfl_xor_sync(0xffffffffu, s3p, 1);
    s3p += __shfl_xor_sync(0xffffffffu, s3p, 2);
    s3p += __shfl_xor_sync(0xffffffffu, s3p, 4);

    if (part == 0)
        out[b] = sigf(s3p + g_c0[0] + g_dot[b] + g_dot[BATCH + b]);
}

// ================= launch =================
extern "C" void kernel_launch(void* const* d_in, const int* in_sizes, int n_in,
                              void* d_out, int out_size)
{
    (void)in_sizes; (void)n_in; (void)out_size;
    const float* x     = (const float*)d_in[0];
    const float* w0ih0 = (const float*)d_in[1];
    const float* w0hh0 = (const float*)d_in[2];
    const float* b0ih0 = (const float*)d_in[3];
    const float* b0hh0 = (const float*)d_in[4];
    const float* w0ih1 = (const float*)d_in[5];
    const float* w0hh1 = (const float*)d_in[6];
    const float* b0ih1 = (const float*)d_in[7];
    const float* b0hh1 = (const float*)d_in[8];
    const float* w1ih0 = (const float*)d_in[9];
    const float* w1hh0 = (const float*)d_in[10];
    const float* b1ih0 = (const float*)d_in[11];
    const float* b1hh0 = (const float*)d_in[12];
    const float* w1ih1 = (const float*)d_in[13];
    const float* w1hh1 = (const float*)d_in[14];
    const float* b1ih1 = (const float*)d_in[15];
    const float* b1hh1 = (const float*)d_in[16];
    const float* Wp    = (const float*)d_in[17];
    const float* bp    = (const float*)d_in[18];
    const float* WH    = (const float*)d_in[19];
    const float* bH    = (const float*)d_in[20];
    const float* WL    = (const float*)d_in[21];
    const float* bL    = (const float*)d_in[22];
    const float* W1    = (const float*)d_in[23];
    const float* b1    = (const float*)d_in[24];
    const float* W2    = (const float*)d_in[25];
    const float* b2    = (const float*)d_in[26];
    const float* W3    = (const float*)d_in[27];
    const float* b3    = (const float*)d_in[28];
    float* out = (float*)d_out;

    prep_u_kernel<<<2, 256>>>(Wp, bp, W3, b3);
    prep_w_kernel<<<16, 256>>>(WH, WL);

    dim3 gl(NBLOCKS, 2);
    lstm_kernel<<<gl, NTHREADS>>>(x,
        w0ih0, w0hh0, b0ih0, b0hh0, w0ih1, w0hh1, b0ih1, b0hh1,
        w1ih0, w1hh0, b1ih0, b1hh0, w1ih1, w1hh1, b1ih1, b1hh1);

    dim3 gf(BATCH / (NTHREADS * 4), 16);
    feat_kernel<<<gf, NTHREADS>>>(bH, bL);

    combine_kernel<<<BATCH * 8 / NTHREADS, NTHREADS>>>(W1, b1, W2, b2, W3, out);
}

// round 12
// speedup vs baseline: 1.2330x; 1.2330x over previous
#include <cuda_runtime.h>

#define BATCH    32768
#define SEQ      200
#define NTHREADS 128
#define NBLOCKS  (BATCH / NTHREADS)

// ---------------- scratch (static __device__, no allocation) ----------------
__device__ float4 g_Hh4[SEQ * BATCH];     // layer-1 h of H RNN, [t][b] = {h0,h1,h2,h3}
__device__ float4 g_Lh4[SEQ * BATCH];     // layer-1 h of L RNN
__device__ float  g_F[256 * BATCH];       // tanh features [Hf(128);Lf(128)] x [b]
__device__ float  g_dot[2 * BATCH];       // x·u partial dots (H part, L part)
__device__ float  g_u[400];               // Wp^T @ W3[40:80]
__device__ float  g_c0[1];                // b3 + bp·W3[40:80]
__device__ float  g_Wt[16 * 800 * 16];    // feat weights [(r*8+jc)][k][j16]

// ---------------- f32x2 packed helpers (Blackwell) ----------------
typedef unsigned long long ull;
__device__ __forceinline__ ull pk(float a, float b) {
    ull r; asm("mov.b64 %0, {%1,%2};" : "=l"(r) : "f"(a), "f"(b)); return r;
}
__device__ __forceinline__ float2 upk(ull v) {
    float2 f; asm("mov.b64 {%0,%1}, %2;" : "=f"(f.x), "=f"(f.y) : "l"(v)); return f;
}
__device__ __forceinline__ ull fma2(ull a, ull b, ull c) {
    ull d; asm("fma.rn.f32x2 %0, %1, %2, %3;" : "=l"(d) : "l"(a), "l"(b), "l"(c));
    return d;
}

// ---------------- activations ----------------
__device__ __forceinline__ float tanha(float x) {       // HW tanh, LSTM-only
    float y; asm("tanh.approx.f32 %0, %1;" : "=f"(y) : "f"(x)); return y;
}
__device__ __forceinline__ float siga(float x) {
    return fmaf(tanha(0.5f * x), 0.5f, 0.5f);
}
__device__ __forceinline__ float sigf(float x) {        // accurate, head
    return __fdividef(1.0f, 1.0f + __expf(-x));
}
__device__ __forceinline__ float tanhfast(float x) {
    return 1.0f - __fdividef(2.0f, __expf(2.0f * x) + 1.0f);
}

// ================= prep A: fold 'other' path into a 400-vector =================
__global__ void prep_u_kernel(const float* __restrict__ Wp, const float* __restrict__ bp,
                              const float* __restrict__ W3, const float* __restrict__ b3)
{
    int k = blockIdx.x * blockDim.x + threadIdx.x;
    if (k < 400) {
        float s = 0.0f;
#pragma unroll
        for (int j = 0; j < 40; j++) s = fmaf(W3[40 + j], Wp[j * 400 + k], s);
        g_u[k] = s;
    }
    if (k == 400) {
        float s = b3[0];
#pragma unroll
        for (int j = 0; j < 40; j++) s = fmaf(W3[40 + j], bp[j], s);
        g_c0[0] = s;
    }
}

// ================= prep B: coalesced transpose of feat weights =================
// g_Wt[blk][k][j] = W_r[(jc*16+j)*800 + k],  blk = r*8+jc,  k in 0..799, j in 0..15
__global__ void prep_w_kernel(const float* __restrict__ WH, const float* __restrict__ WL)
{
    __shared__ float sT[16][401];
    const int blk = blockIdx.x;            // 0..15
    const int r = blk >> 3, jc = blk & 7;
    const float* __restrict__ W = r ? WL : WH;
    const int tid = threadIdx.x;           // 256 threads
    float* __restrict__ dst = g_Wt + (size_t)blk * 800 * 16;

    for (int half = 0; half < 2; half++) {
        __syncthreads();
        for (int idx = tid; idx < 16 * 400; idx += 256) {
            int j = idx / 400, k = idx % 400;
            sT[j][k] = W[(size_t)(jc * 16 + j) * 800 + half * 400 + k];
        }
        __syncthreads();
        for (int idx = tid; idx < 400 * 16; idx += 256) {
            int k = idx >> 4, j = idx & 15;
            dst[(half * 400 + k) * 16 + j] = sT[j][k];
        }
    }
}

// ================= LSTM cell (H=4, gate order i,f,g,o) =================
__device__ __forceinline__ void cell_update(const float* g, float* h, float* c) {
#pragma unroll
    for (int k = 0; k < 4; k++) {
        float cn = siga(g[4 + k]) * c[k] + siga(g[k]) * tanha(g[8 + k]);
        c[k] = cn;
        h[k] = siga(g[12 + k]) * tanha(cn);
    }
}

// ================= Kernel 1: 2-layer LSTM, software-pipelined layers ============
// Iteration t computes layer0(t) and layer1(t-1) concurrently: both depend only
// on h0(t-1), so their dependency chains run in parallel (ILP 2, chain ~halved).
__global__ __launch_bounds__(NTHREADS) void lstm_kernel(
    const float* __restrict__ x,
    const float* __restrict__ w0ih0, const float* __restrict__ w0hh0,
    const float* __restrict__ b0ih0, const float* __restrict__ b0hh0,
    const float* __restrict__ w0ih1, const float* __restrict__ w0hh1,
    const float* __restrict__ b0ih1, const float* __restrict__ b0hh1,
    const float* __restrict__ w1ih0, const float* __restrict__ w1hh0,
    const float* __restrict__ b1ih0, const float* __restrict__ b1hh0,
    const float* __restrict__ w1ih1, const float* __restrict__ w1hh1,
    const float* __restrict__ b1ih1, const float* __restrict__ b1hh1)
{
    __shared__ ull sWih0[8], sB0[8], sB1[8];
    __shared__ ull sWhh0[32], sWih1[32], sWhh1[32];   // [k][pair] = k*8+p
    __shared__ float sX[NTHREADS][25];

    const int tid = threadIdx.x;
    const int ch  = blockIdx.y;
    const int b0  = blockIdx.x * NTHREADS;
    const int b   = b0 + tid;

    const float* wih0 = ch ? w1ih0 : w0ih0;
    const float* whh0 = ch ? w1hh0 : w0hh0;
    const float* bi0  = ch ? b1ih0 : b0ih0;
    const float* bh0  = ch ? b1hh0 : b0hh0;
    const float* wih1 = ch ? w1ih1 : w0ih1;
    const float* whh1 = ch ? w1hh1 : w0hh1;
    const float* bi1  = ch ? b1ih1 : b0ih1;
    const float* bh1  = ch ? b1hh1 : b0hh1;
    float4* __restrict__ hout4 = ch ? g_Lh4 : g_Hh4;

    if (tid < 8) {
        int p = tid;
        sWih0[p] = pk(wih0[2 * p], wih0[2 * p + 1]);
        sB0[p]   = pk(bi0[2 * p] + bh0[2 * p], bi0[2 * p + 1] + bh0[2 * p + 1]);
        sB1[p]   = pk(bi1[2 * p] + bh1[2 * p], bi1[2 * p + 1] + bh1[2 * p + 1]);
    }
    if (tid < 32) {
        int k = tid >> 3, p = tid & 7;
        sWhh0[tid] = pk(whh0[(2 * p) * 4 + k], whh0[(2 * p + 1) * 4 + k]);
        sWih1[tid] = pk(wih1[(2 * p) * 4 + k], wih1[(2 * p + 1) * 4 + k]);
        sWhh1[tid] = pk(whh1[(2 * p) * 4 + k], whh1[(2 * p + 1) * 4 + k]);
    }

    float h0[4], c0a[4], h1[4], c1[4];
#pragma unroll
    for (int k = 0; k < 4; k++) { h0[k] = c0a[k] = h1[k] = c1[k] = 0.0f; }
    float dacc = 0.0f;
    const float* uvec = g_u + ch * SEQ;

    for (int tile = 0; tile < 8; ++tile) {
        __syncthreads();
#pragma unroll
        for (int i = tid; i < NTHREADS * 25; i += NTHREADS) {
            int s = i / 25, tt = i % 25;
            sX[s][tt] = x[(size_t)(b0 + s) * (2 * SEQ) + ch * SEQ + tile * 25 + tt];
        }
        __syncthreads();

        for (int tt = 0; tt < 25; ++tt) {
            const int t = tile * 25 + tt;
            const float xh = sX[tid][tt];
            dacc = fmaf(xh, __ldg(&uvec[t]), dacc);

            // snapshot h0(t-1): consumed by BOTH layer0(t) and layer1(t-1)
            float h0in[4];
#pragma unroll
            for (int k = 0; k < 4; k++) h0in[k] = h0[k];

            // ---- layer0(t) gates (chain A) ----
            ull v0[8];
            {
                ull x2 = pk(xh, xh);
#pragma unroll
                for (int p = 0; p < 8; p++) v0[p] = fma2(x2, sWih0[p], sB0[p]);
#pragma unroll
                for (int k = 0; k < 4; k++) {
                    ull h2 = pk(h0in[k], h0in[k]);
#pragma unroll
                    for (int p = 0; p < 8; p++) v0[p] = fma2(h2, sWhh0[k * 8 + p], v0[p]);
                }
            }
            // ---- layer1(t-1) gates (chain B, independent of chain A) ----
            ull v1[8];
#pragma unroll
            for (int p = 0; p < 8; p++) v1[p] = sB1[p];
#pragma unroll
            for (int k = 0; k < 4; k++) {
                ull h2 = pk(h0in[k], h0in[k]);
#pragma unroll
                for (int p = 0; p < 8; p++) v1[p] = fma2(h2, sWih1[k * 8 + p], v1[p]);
            }
#pragma unroll
            for (int k = 0; k < 4; k++) {
                ull h2 = pk(h1[k], h1[k]);
#pragma unroll
                for (int p = 0; p < 8; p++) v1[p] = fma2(h2, sWhh1[k * 8 + p], v1[p]);
            }

            float g0[16];
#pragma unroll
            for (int p = 0; p < 8; p++) { float2 f = upk(v0[p]); g0[2 * p] = f.x; g0[2 * p + 1] = f.y; }
            cell_update(g0, h0, c0a);

            if (t > 0) {   // layer1 result for step t-1 (h1,c1 stay 0 at t=0)
                float g1[16];
#pragma unroll
                for (int p = 0; p < 8; p++) { float2 f = upk(v1[p]); g1[2 * p] = f.x; g1[2 * p + 1] = f.y; }
                cell_update(g1, h1, c1);
                hout4[(size_t)(t - 1) * BATCH + b] = make_float4(h1[0], h1[1], h1[2], h1[3]);
            }
        }
    }

    // epilogue: layer1(199) from final h0
    {
        ull v1[8];
#pragma unroll
        for (int p = 0; p < 8; p++) v1[p] = sB1[p];
#pragma unroll
        for (int k = 0; k < 4; k++) {
            ull h2 = pk(h0[k], h0[k]);
#pragma unroll
            for (int p = 0; p < 8; p++) v1[p] = fma2(h2, sWih1[k * 8 + p], v1[p]);
        }
#pragma unroll
        for (int k = 0; k < 4; k++) {
            ull h2 = pk(h1[k], h1[k]);
#pragma unroll
            for (int p = 0; p < 8; p++) v1[p] = fma2(h2, sWhh1[k * 8 + p], v1[p]);
        }
        float g1[16];
#pragma unroll
        for (int p = 0; p < 8; p++) { float2 f = upk(v1[p]); g1[2 * p] = f.x; g1[2 * p + 1] = f.y; }
        cell_update(g1, h1, c1);
        hout4[(size_t)199 * BATCH + b] = make_float4(h1[0], h1[1], h1[2], h1[3]);
    }
    g_dot[ch * BATCH + b] = dacc;
}

// ================= Kernel 2: feature GEMM, 4 samples x 16 features / thread ======
// grid (BATCH/512, 16): y = r*8+jc
__global__ __launch_bounds__(NTHREADS) void feat_kernel(
    const float* __restrict__ bHv, const float* __restrict__ bLv)
{
    __shared__ __align__(16) float sW[400 * 16];     // 25.6 KB, [k-local][j]

    const int tid = threadIdx.x;
    const int bb0 = blockIdx.x * (NTHREADS * 4);
    const int y   = blockIdx.y;
    const int r   = y >> 3, jc = y & 7;
    const float*  __restrict__ bias = r ? bLv : bHv;
    const float4* __restrict__ hh4  = r ? g_Lh4 : g_Hh4;
    const int f0 = jc * 16;

    ull acc[4][8];
#pragma unroll
    for (int p = 0; p < 8; p++) {
        ull bv = pk(__ldg(&bias[f0 + 2 * p]), __ldg(&bias[f0 + 2 * p + 1]));
#pragma unroll
        for (int s = 0; s < 4; s++) acc[s][p] = bv;
    }

    const float* wt_base = g_Wt + (size_t)y * 800 * 16;

    for (int half = 0; half < 2; half++) {
        __syncthreads();
        const float4* src = reinterpret_cast<const float4*>(wt_base + half * 400 * 16);
#pragma unroll
        for (int i4 = tid; i4 < 1600; i4 += NTHREADS)
            reinterpret_cast<float4*>(sW)[i4] = __ldg(&src[i4]);
        __syncthreads();

#pragma unroll 1
        for (int tt = 0; tt < 100; ++tt) {
            const int t = half * 100 + tt;
            float ha[4][4];
#pragma unroll
            for (int s = 0; s < 4; s++) {
                float4 hv = __ldg(&hh4[(size_t)t * BATCH + bb0 + s * NTHREADS + tid]);
                ha[s][0] = hv.x; ha[s][1] = hv.y; ha[s][2] = hv.z; ha[s][3] = hv.w;
            }
#pragma unroll
            for (int kk = 0; kk < 4; kk++) {
                const ulonglong2* wp =
                    reinterpret_cast<const ulonglong2*>(sW + (tt * 4 + kk) * 16);
                ulonglong2 w0 = wp[0], w1 = wp[1], w2 = wp[2], w3 = wp[3];
#pragma unroll
                for (int s = 0; s < 4; s++) {
                    ull hd = pk(ha[s][kk], ha[s][kk]);
                    acc[s][0] = fma2(hd, w0.x, acc[s][0]);
                    acc[s][1] = fma2(hd, w0.y, acc[s][1]);
                    acc[s][2] = fma2(hd, w1.x, acc[s][2]);
                    acc[s][3] = fma2(hd, w1.y, acc[s][3]);
                    acc[s][4] = fma2(hd, w2.x, acc[s][4]);
                    acc[s][5] = fma2(hd, w2.y, acc[s][5]);
                    acc[s][6] = fma2(hd, w3.x, acc[s][6]);
                    acc[s][7] = fma2(hd, w3.y, acc[s][7]);
                }
            }
        }
    }

#pragma unroll
    for (int s = 0; s < 4; s++) {
        const int b = bb0 + s * NTHREADS + tid;
#pragma unroll
        for (int p = 0; p < 8; p++) {
            float2 f = upk(acc[s][p]);
            g_F[(size_t)(r * 128 + f0 + 2 * p) * BATCH + b]     = tanhfast(f.x);
            g_F[(size_t)(r * 128 + f0 + 2 * p + 1) * BATCH + b] = tanhfast(f.y);
        }
    }
}

// ================= Kernel 3: combine  256 -> 80 -> 40 -> 1  (4 threads/sample) ====
__global__ __launch_bounds__(NTHREADS) void combine_kernel(
    const float* __restrict__ W1, const float* __restrict__ b1,
    const float* __restrict__ W2, const float* __restrict__ b2,
    const float* __restrict__ W3,
    float* __restrict__ out)
{
    const int tid  = threadIdx.x;
    const int part = tid & 3;                       // which quarter of features
    const int b    = blockIdx.x * 32 + (tid >> 2);  // sample

    float acc1[80];
#pragma unroll
    for (int i = 0; i < 80; i++) acc1[i] = 0.0f;

#pragma unroll 1
    for (int q = 0; q < 16; ++q) {                  // 16 quads = 64 features per lane
        const int f0 = part * 64 + 4 * q;
        const float* fp = g_F + (size_t)f0 * BATCH + b;
        float v0 = __ldg(fp);
        float v1 = __ldg(fp + BATCH);
        float v2 = __ldg(fp + 2 * BATCH);
        float v3 = __ldg(fp + 3 * BATCH);
#pragma unroll
        for (int i = 0; i < 80; i++) {
            float4 w = __ldg(reinterpret_cast<const float4*>(W1 + (size_t)i * 256 + f0));
            float s = acc1[i];
            s = fmaf(v0, w.x, s);
            s = fmaf(v1, w.y, s);
            s = fmaf(v2, w.z, s);
            acc1[i] = fmaf(v3, w.w, s);
        }
    }
    // reduce partial acc1 across the 4-lane group, add bias, tanh
#pragma unroll
    for (int i = 0; i < 80; i++) {
        float s = acc1[i];
        s += __shfl_xor_sync(0xffffffffu, s, 1);
        s += __shfl_xor_sync(0xffffffffu, s, 2);
        acc1[i] = tanhfast(s + __ldg(&b1[i]));
    }

    // each lane handles 10 of the 40 W2 rows, folded into the final dot
    float s3p = 0.0f;
#pragma unroll 1
    for (int r10 = 0; r10 < 10; ++r10) {
        const int i2 = part * 10 + r10;
        float s = __ldg(&b2[i2]);
        const float4* w4 = reinterpret_cast<const float4*>(W2 + (size_t)i2 * 80);
#pragma unroll
        for (int j4 = 0; j4 < 20; j4++) {
            float4 w = __ldg(&w4[j4]);
            s = fmaf(acc1[4 * j4 + 0], w.x, s);
            s = fmaf(acc1[4 * j4 + 1], w.y, s);
            s = fmaf(acc1[4 * j4 + 2], w.z, s);
            s = fmaf(acc1[4 * j4 + 3], w.w, s);
        }
        s3p = fmaf(tanhfast(s), __ldg(&W3[i2]), s3p);
    }
    s3p += __shfl_xor_sync(0xffffffffu, s3p, 1);
    s3p += __shfl_xor_sync(0xffffffffu, s3p, 2);

    if (part == 0)
        out[b] = sigf(s3p + g_c0[0] + g_dot[b] + g_dot[BATCH + b]);
}

// ================= launch =================
extern "C" void kernel_launch(void* const* d_in, const int* in_sizes, int n_in,
                              void* d_out, int out_size)
{
    (void)in_sizes; (void)n_in; (void)out_size;
    const float* x     = (const float*)d_in[0];
    const float* w0ih0 = (const float*)d_in[1];
    const float* w0hh0 = (const float*)d_in[2];
    const float* b0ih0 = (const float*)d_in[3];
    const float* b0hh0 = (const float*)d_in[4];
    const float* w0ih1 = (const float*)d_in[5];
    const float* w0hh1 = (const float*)d_in[6];
    const float* b0ih1 = (const float*)d_in[7];
    const float* b0hh1 = (const float*)d_in[8];
    const float* w1ih0 = (const float*)d_in[9];
    const float* w1hh0 = (const float*)d_in[10];
    const float* b1ih0 = (const float*)d_in[11];
    const float* b1hh0 = (const float*)d_in[12];
    const float* w1ih1 = (const float*)d_in[13];
    const float* w1hh1 = (const float*)d_in[14];
    const float* b1ih1 = (const float*)d_in[15];
    const float* b1hh1 = (const float*)d_in[16];
    const float* Wp    = (const float*)d_in[17];
    const float* bp    = (const float*)d_in[18];
    const float* WH    = (const float*)d_in[19];
    const float* bH    = (const float*)d_in[20];
    const float* WL    = (const float*)d_in[21];
    const float* bL    = (const float*)d_in[22];
    const float* W1    = (const float*)d_in[23];
    const float* b1    = (const float*)d_in[24];
    const float* W2    = (const float*)d_in[25];
    const float* b2    = (const float*)d_in[26];
    const float* W3    = (const float*)d_in[27];
    const float* b3    = (const float*)d_in[28];
    float* out = (float*)d_out;

    prep_u_kernel<<<2, 256>>>(Wp, bp, W3, b3);
    prep_w_kernel<<<16, 256>>>(WH, WL);

    dim3 gl(NBLOCKS, 2);
    lstm_kernel<<<gl, NTHREADS>>>(x,
        w0ih0, w0hh0, b0ih0, b0hh0, w0ih1, w0hh1, b0ih1, b0hh1,
        w1ih0, w1hh0, b1ih0, b1hh0, w1ih1, w1hh1, b1ih1, b1hh1);

    dim3 gf(BATCH / (NTHREADS * 4), 16);
    feat_kernel<<<gf, NTHREADS>>>(bH, bL);

    combine_kernel<<<BATCH * 4 / NTHREADS, NTHREADS>>>(W1, b1, W2, b2, W3, out);
}